// round 1
// baseline (speedup 1.0000x reference)
#include <cuda_runtime.h>
#include <cuda_bf16.h>

#define BATCH 32
#define LSEQ  1025
#define NTOK  513
#define TLEN  2048
#define EMB   384
#define TT    32      // frames per tile
#define CH    64      // token chunk size
#define NTH   384     // threads per block (== EMB)
#define RW    46.0f   // window half-width in frames (exact fp32-zero beyond)

__device__ float4 g_tok[BATCH][NTOK];   // {center, 1/sig, coef(0 if PAD), token_id as bits}
__device__ float  g_cumend[BATCH];

// ---------------- Kernel A: merge + scan + token params ----------------
__global__ void prep_kernel(const int* __restrict__ text, const int* __restrict__ durs) {
    int b = blockIdx.x;
    int i = threadIdx.x;
    __shared__ float a[NTOK];
    float d = 0.0f; int tx = 0;
    if (i < NTOK) {
        if (i == 0) { d = (float)durs[b * LSEQ]; tx = text[b * LSEQ]; }
        else {
            d  = (float)(durs[b * LSEQ + 2 * i - 1] + durs[b * LSEQ + 2 * i]);
            tx = text[b * LSEQ + 2 * i - 1];
        }
        a[i] = d;
    }
    __syncthreads();
    // Hillis-Steele inclusive scan over NTOK elements
    for (int off = 1; off < NTOK; off <<= 1) {
        float v = 0.0f;
        if (i < NTOK) { v = a[i]; if (i >= off) v += a[i - off]; }
        __syncthreads();
        if (i < NTOK) a[i] = v;
        __syncthreads();
    }
    if (i < NTOK) {
        float cum  = a[i];
        float c    = cum - 0.5f * d;
        float sig  = 0.5f * d + 1e-6f;        // d / SIGMA_C + EPS, SIGMA_C = 2
        float invs = 1.0f / sig;
        float coef = (tx == 0) ? 0.0f : invs * 0.3989422804014327f; // 1/(sig*sqrt(2pi)), PAD->0
        g_tok[b][i] = make_float4(c, invs, coef, __int_as_float(tx));
        if (i == NTOK - 1) g_cumend[b] = cum;
    }
}

// ---------------- Kernel B: windowed gaussian upsample ----------------
__global__ void __launch_bounds__(NTH, 2)
gauss_kernel(const float* __restrict__ emb, float* __restrict__ out) {
    const int b  = blockIdx.y;
    const int t0 = blockIdx.x * TT;
    const int tid = threadIdx.x;          // tid == embedding column e

    __shared__ __align__(16) float w_s[CH][TT];
    __shared__ float wsum[TT];
    __shared__ float scale[TT];
    __shared__ float s_c[CH], s_is[CH], s_cf[CH];
    __shared__ int   s_tok[CH];
    __shared__ int   s_lo, s_hi;

    if (tid < TT) wsum[tid] = 0.0f;
    if (tid == 0) { s_lo = NTOK; s_hi = 0; }
    __syncthreads();

    // ---- find token window [nlo, nhi) via parallel min/max over monotone centers ----
    {
        const float lo = (float)t0 + 0.5f - RW;
        const float hi = (float)t0 + (float)TT - 0.5f + RW;
        for (int n = tid; n < NTOK; n += NTH) {
            float c = g_tok[b][n].x;
            if (c >= lo) atomicMin(&s_lo, n);
            if (c <= hi) atomicMax(&s_hi, n + 1);
        }
    }
    __syncthreads();
    int nlo = s_lo;
    int nhi = s_hi;
    if (nhi < nlo) nhi = nlo;

    float acc[TT];
#pragma unroll
    for (int t = 0; t < TT; ++t) acc[t] = 0.0f;

    const float cumend = g_cumend[b];

    for (int cs = nlo; cs < nhi; cs += CH) {
        const int cnt = min(CH, nhi - cs);
        // stage token params
        if (tid < cnt) {
            float4 p = g_tok[b][cs + tid];
            s_c[tid]  = p.x;
            s_is[tid] = p.y;
            s_cf[tid] = p.z;
            s_tok[tid] = __float_as_int(p.w);
        }
        __syncthreads();
        // phase 1: weights into smem + wsum
        for (int idx = tid; idx < cnt * TT; idx += NTH) {
            int nl = idx >> 5;
            int tt = idx & (TT - 1);
            float tm = (float)(t0 + tt) + 0.5f;
            float z  = (tm - s_c[nl]) * s_is[nl];
            float w  = s_cf[nl] * __expf(-0.5f * z * z);
            w_s[nl][tt] = w;
            atomicAdd(&wsum[tt], w);
        }
        __syncthreads();
        // phase 2: acc[t] += w[t] * emb[tok][e], thread owns column e = tid
        float ev = (cnt > 0) ? emb[s_tok[0] * EMB + tid] : 0.0f;
        for (int nl = 0; nl < cnt; ++nl) {
            float evn = (nl + 1 < cnt) ? emb[s_tok[nl + 1] * EMB + tid] : 0.0f;
            const float4* wp = reinterpret_cast<const float4*>(w_s[nl]);
#pragma unroll
            for (int j = 0; j < TT / 4; ++j) {
                float4 w4 = wp[j];
                acc[4 * j + 0] += w4.x * ev;
                acc[4 * j + 1] += w4.y * ev;
                acc[4 * j + 2] += w4.z * ev;
                acc[4 * j + 3] += w4.w * ev;
            }
            ev = evn;
        }
        __syncthreads();
    }

    // ---- normalization + validity scales ----
    if (tid < TT) {
        float tm = (float)(t0 + tid) + 0.5f;
        scale[tid] = (tm < cumend) ? (1.0f / (wsum[tid] + 1e-6f)) : 0.0f;
    }
    __syncthreads();

#pragma unroll
    for (int tt = 0; tt < TT; ++tt) {
        out[((size_t)(b * TLEN + t0 + tt)) * EMB + tid] = acc[tt] * scale[tt];
    }
}

extern "C" void kernel_launch(void* const* d_in, const int* in_sizes, int n_in,
                              void* d_out, int out_size) {
    const int*   text = (const int*)d_in[0];
    const int*   durs = (const int*)d_in[1];
    const float* emb  = (const float*)d_in[2];
    float* out = (float*)d_out;

    prep_kernel<<<BATCH, 544>>>(text, durs);
    dim3 grid(TLEN / TT, BATCH);
    gauss_kernel<<<grid, NTH>>>(emb, out);
}

// round 2
// speedup vs baseline: 1.9133x; 1.9133x over previous
#include <cuda_runtime.h>
#include <cuda_bf16.h>

#define BATCH  32
#define LSEQ   1025
#define NTOK   513
#define TLEN   2048
#define EMB    384
#define TT     32            // frames per tile
#define NTILES (TLEN / TT)   // 64
#define NTH    192           // threads per block; each owns 2 embedding cols
#define CHMAX  88            // max compacted tokens per tile (worst case ~75)

__device__ float4 g_tok[BATCH][NTOK];   // {center, 1/sig, reach (−1e30 if dropped), token_id bits}
__device__ float  g_cumend[BATCH];
__device__ int    g_wlo[BATCH][NTILES];
__device__ int    g_whi[BATCH][NTILES];

// ---------------- Kernel A: merge + scan + token params + per-tile windows ----------------
__global__ void prep_kernel(const int* __restrict__ text, const int* __restrict__ durs) {
    int b = blockIdx.x;
    int i = threadIdx.x;
    __shared__ float a[NTOK];

    if (i < NTILES) { g_wlo[b][i] = NTOK; g_whi[b][i] = 0; }

    float d = 0.0f; int tx = 0;
    if (i < NTOK) {
        if (i == 0) { d = (float)durs[b * LSEQ]; tx = text[b * LSEQ]; }
        else {
            d  = (float)(durs[b * LSEQ + 2 * i - 1] + durs[b * LSEQ + 2 * i]);
            tx = text[b * LSEQ + 2 * i - 1];
        }
        a[i] = d;
    }
    __syncthreads();
    // Hillis-Steele inclusive scan
    for (int off = 1; off < NTOK; off <<= 1) {
        float v = 0.0f;
        if (i < NTOK) { v = a[i]; if (i >= off) v += a[i - off]; }
        __syncthreads();
        if (i < NTOK) a[i] = v;
        __syncthreads();
    }
    if (i < NTOK) {
        float cum  = a[i];
        float c    = cum - 0.5f * d;
        float sig  = 0.5f * d + 1e-6f;
        float invs = 1.0f / sig;
        bool  kept = (tx != 0) && (d > 0.0f);
        // z-cut = 7: truncated weights < 1.7e-11 << eps=1e-6 in normalizer
        float r = kept ? (3.5f * d + 0.51f) : -1e30f;
        g_tok[b][i] = make_float4(c, invs, r, __int_as_float(tx));
        if (kept) {
            int k0 = max(0, (int)ceilf((c - r - ((float)TT - 0.5f)) * (1.0f / TT)));
            int k1 = min(NTILES - 1, (int)floorf((c + r - 0.5f) * (1.0f / TT)));
            for (int k = k0; k <= k1; ++k) {
                atomicMin(&g_wlo[b][k], i);
                atomicMax(&g_whi[b][k], i + 1);
            }
        }
        if (i == NTOK - 1) g_cumend[b] = cum;
    }
}

// ---------------- Kernel B: windowed gaussian upsample ----------------
__global__ void __launch_bounds__(NTH)
gauss_kernel(const float* __restrict__ emb, float* __restrict__ out) {
    const int b   = blockIdx.y;
    const int tile = blockIdx.x;
    const int t0  = tile * TT;
    const int tid = threadIdx.x;       // owns embedding cols 2*tid, 2*tid+1

    __shared__ __align__(16) float w_s[CHMAX][TT];
    __shared__ float s_c[CHMAX], s_is[CHMAX], s_cf[CHMAX];
    __shared__ int   s_tok[CHMAX];
    __shared__ float wsum[TT], scale_s[TT];
    __shared__ int   s_cnt;

    if (tid < TT) wsum[tid] = 0.0f;
    if (tid == 0) s_cnt = 0;
    __syncthreads();

    // ---- compact per-token-reach-filtered token list for this tile ----
    const float tlo = (float)t0 + 0.5f;
    const float thi = (float)t0 + (float)TT - 0.5f;
    {
        const int nlo = g_wlo[b][tile];
        const int nhi = g_whi[b][tile];
        for (int n = nlo + tid; n < nhi; n += NTH) {
            float4 p = g_tok[b][n];
            if (p.x - p.z <= thi && p.x + p.z >= tlo) {
                int s = atomicAdd(&s_cnt, 1);
                if (s < CHMAX) {
                    s_c[s]   = p.x;
                    s_is[s]  = p.y;
                    s_cf[s]  = 0.3989422804014327f * p.y;
                    s_tok[s] = __float_as_int(p.w);
                }
            }
        }
    }
    __syncthreads();
    const int cnt = min(s_cnt, CHMAX);

    // ---- phase 1: weights -> smem; per-thread register wsum (tt fixed = tid&31) ----
    {
        const int   myt = tid & (TT - 1);
        const float tm  = (float)(t0 + myt) + 0.5f;
        float wl = 0.0f;
        for (int idx = tid; idx < cnt * TT; idx += NTH) {
            int nl = idx >> 5;
            float z = (tm - s_c[nl]) * s_is[nl];
            float w = s_cf[nl] * __expf(-0.5f * z * z);
            w_s[nl][myt] = w;
            wl += w;
        }
        atomicAdd(&wsum[myt], wl);
    }
    __syncthreads();

    if (tid < TT) {
        float tmv = (float)(t0 + tid) + 0.5f;
        scale_s[tid] = (tmv < g_cumend[b]) ? (1.0f / (wsum[tid] + 1e-6f)) : 0.0f;
    }

    // ---- phase 2: acc[t] += w[t] * emb[tok][2tid..2tid+1] ----
    float2 acc[TT];
#pragma unroll
    for (int t = 0; t < TT; ++t) acc[t] = make_float2(0.0f, 0.0f);

    const float2* embp = reinterpret_cast<const float2*>(emb);
    float2 ev = make_float2(0.0f, 0.0f);
    if (cnt > 0) ev = embp[s_tok[0] * (EMB / 2) + tid];
    for (int nl = 0; nl < cnt; ++nl) {
        float2 evn = (nl + 1 < cnt) ? embp[s_tok[nl + 1] * (EMB / 2) + tid]
                                    : make_float2(0.0f, 0.0f);
        const float4* wp = reinterpret_cast<const float4*>(w_s[nl]);
#pragma unroll
        for (int j = 0; j < TT / 4; ++j) {
            float4 w4 = wp[j];
            acc[4 * j + 0].x += w4.x * ev.x;  acc[4 * j + 0].y += w4.x * ev.y;
            acc[4 * j + 1].x += w4.y * ev.x;  acc[4 * j + 1].y += w4.y * ev.y;
            acc[4 * j + 2].x += w4.z * ev.x;  acc[4 * j + 2].y += w4.z * ev.y;
            acc[4 * j + 3].x += w4.w * ev.x;  acc[4 * j + 3].y += w4.w * ev.y;
        }
        ev = evn;
    }
    __syncthreads();   // scale_s ready

    // ---- normalize + store (float2, coalesced per frame) ----
    float2* outp = reinterpret_cast<float2*>(out);
    size_t base = ((size_t)(b * TLEN + t0)) * (EMB / 2) + tid;
#pragma unroll
    for (int tt = 0; tt < TT; ++tt) {
        float s = scale_s[tt];
        float2 v = make_float2(acc[tt].x * s, acc[tt].y * s);
        outp[base + (size_t)tt * (EMB / 2)] = v;
    }
}

extern "C" void kernel_launch(void* const* d_in, const int* in_sizes, int n_in,
                              void* d_out, int out_size) {
    const int*   text = (const int*)d_in[0];
    const int*   durs = (const int*)d_in[1];
    const float* emb  = (const float*)d_in[2];
    float* out = (float*)d_out;

    prep_kernel<<<BATCH, 544>>>(text, durs);
    dim3 grid(NTILES, BATCH);
    gauss_kernel<<<grid, NTH>>>(emb, out);
}

// round 3
// speedup vs baseline: 2.2134x; 1.1568x over previous
#include <cuda_runtime.h>
#include <cuda_bf16.h>

#define BATCH  32
#define LSEQ   1025
#define NTOK   513
#define TLEN   2048
#define EMB    384
#define TT     16            // frames per tile
#define NTILES (TLEN / TT)   // 128
#define NTH    192           // threads per block; each owns 2 embedding cols
#define CHMAX  64            // max compacted tokens per tile (worst case ~24)

__device__ float4 g_tok[BATCH][NTOK];   // {center, 1/sig, reach (-1e30 if dropped), token_id bits}
__device__ float  g_cumend[BATCH];
__device__ int    g_wlo[BATCH][NTILES];
__device__ int    g_whi[BATCH][NTILES];

// ---------------- Kernel A: merge + scan + token params + per-tile windows ----------------
__global__ void prep_kernel(const int* __restrict__ text, const int* __restrict__ durs) {
    int b = blockIdx.x;
    int i = threadIdx.x;
    __shared__ float a[NTOK];

    if (i < NTILES) { g_wlo[b][i] = NTOK; g_whi[b][i] = 0; }

    float d = 0.0f; int tx = 0;
    if (i < NTOK) {
        if (i == 0) { d = (float)durs[b * LSEQ]; tx = text[b * LSEQ]; }
        else {
            d  = (float)(durs[b * LSEQ + 2 * i - 1] + durs[b * LSEQ + 2 * i]);
            tx = text[b * LSEQ + 2 * i - 1];
        }
        a[i] = d;
    }
    __syncthreads();
    // Hillis-Steele inclusive scan
    for (int off = 1; off < NTOK; off <<= 1) {
        float v = 0.0f;
        if (i < NTOK) { v = a[i]; if (i >= off) v += a[i - off]; }
        __syncthreads();
        if (i < NTOK) a[i] = v;
        __syncthreads();
    }
    if (i < NTOK) {
        float cum  = a[i];
        float c    = cum - 0.5f * d;
        float sig  = 0.5f * d + 1e-6f;
        float invs = 1.0f / sig;
        bool  kept = (tx != 0) && (d > 0.0f);
        // z-cut = 7: truncated weights < 1.7e-11 << eps=1e-6 in normalizer
        float r = kept ? (3.5f * d + 0.51f) : -1e30f;
        g_tok[b][i] = make_float4(c, invs, r, __int_as_float(tx));
        if (kept) {
            int k0 = max(0, (int)ceilf((c - r - ((float)TT - 0.5f)) * (1.0f / TT)));
            int k1 = min(NTILES - 1, (int)floorf((c + r - 0.5f) * (1.0f / TT)));
            for (int k = k0; k <= k1; ++k) {
                atomicMin(&g_wlo[b][k], i);
                atomicMax(&g_whi[b][k], i + 1);
            }
        }
        if (i == NTOK - 1) g_cumend[b] = cum;
    }
}

// ---------------- Kernel B: windowed gaussian upsample ----------------
__global__ void __launch_bounds__(NTH, 5)
gauss_kernel(const float* __restrict__ emb, float* __restrict__ out) {
    const int b    = blockIdx.y;
    const int tile = blockIdx.x;
    const int t0   = tile * TT;
    const int tid  = threadIdx.x;       // owns embedding cols 2*tid, 2*tid+1

    __shared__ __align__(16) float w_s[CHMAX][TT];
    __shared__ float s_c[CHMAX], s_is[CHMAX], s_cf[CHMAX];
    __shared__ int   s_tok[CHMAX];
    __shared__ float wsum[TT], scale_s[TT];
    __shared__ int   s_cnt;

    if (tid < TT) wsum[tid] = 0.0f;
    if (tid == 0) s_cnt = 0;
    __syncthreads();

    // ---- compact per-token-reach-filtered token list for this tile ----
    const float tlo = (float)t0 + 0.5f;
    const float thi = (float)t0 + (float)TT - 0.5f;
    {
        const int nlo = g_wlo[b][tile];
        const int nhi = g_whi[b][tile];
        for (int n = nlo + tid; n < nhi; n += NTH) {
            float4 p = g_tok[b][n];
            if (p.x - p.z <= thi && p.x + p.z >= tlo) {
                int s = atomicAdd(&s_cnt, 1);
                if (s < CHMAX) {
                    s_c[s]   = p.x;
                    s_is[s]  = p.y;
                    s_cf[s]  = 0.3989422804014327f * p.y;
                    s_tok[s] = __float_as_int(p.w);
                }
            }
        }
    }
    __syncthreads();
    const int cnt = min(s_cnt, CHMAX);

    // ---- phase 1: weights -> smem; per-thread register wsum (frame fixed = tid & 15) ----
    {
        const int   myt = tid & (TT - 1);
        const float tm  = (float)(t0 + myt) + 0.5f;
        float wl = 0.0f;
        for (int idx = tid; idx < cnt * TT; idx += NTH) {
            int nl = idx >> 4;
            float z = (tm - s_c[nl]) * s_is[nl];
            float w = s_cf[nl] * __expf(-0.5f * z * z);
            w_s[nl][myt] = w;
            wl += w;
        }
        atomicAdd(&wsum[myt], wl);
    }
    __syncthreads();

    if (tid < TT) {
        float tmv = (float)(t0 + tid) + 0.5f;
        scale_s[tid] = (tmv < g_cumend[b]) ? (1.0f / (wsum[tid] + 1e-6f)) : 0.0f;
    }

    // ---- phase 2: acc[t] += w[t] * emb[tok][2tid..2tid+1] ----
    float2 acc[TT];
#pragma unroll
    for (int t = 0; t < TT; ++t) acc[t] = make_float2(0.0f, 0.0f);

    const float2* embp = reinterpret_cast<const float2*>(emb);
    float2 ev = make_float2(0.0f, 0.0f);
    if (cnt > 0) ev = embp[s_tok[0] * (EMB / 2) + tid];
    for (int nl = 0; nl < cnt; ++nl) {
        float2 evn = (nl + 1 < cnt) ? embp[s_tok[nl + 1] * (EMB / 2) + tid]
                                    : make_float2(0.0f, 0.0f);
        const float4* wp = reinterpret_cast<const float4*>(w_s[nl]);
#pragma unroll
        for (int j = 0; j < TT / 4; ++j) {
            float4 w4 = wp[j];
            acc[4 * j + 0].x += w4.x * ev.x;  acc[4 * j + 0].y += w4.x * ev.y;
            acc[4 * j + 1].x += w4.y * ev.x;  acc[4 * j + 1].y += w4.y * ev.y;
            acc[4 * j + 2].x += w4.z * ev.x;  acc[4 * j + 2].y += w4.z * ev.y;
            acc[4 * j + 3].x += w4.w * ev.x;  acc[4 * j + 3].y += w4.w * ev.y;
        }
        ev = evn;
    }
    __syncthreads();   // scale_s ready

    // ---- normalize + store (float2, coalesced per frame) ----
    float2* outp = reinterpret_cast<float2*>(out);
    size_t base = ((size_t)(b * TLEN + t0)) * (EMB / 2) + tid;
#pragma unroll
    for (int tt = 0; tt < TT; ++tt) {
        float s = scale_s[tt];
        float2 v = make_float2(acc[tt].x * s, acc[tt].y * s);
        outp[base + (size_t)tt * (EMB / 2)] = v;
    }
}

extern "C" void kernel_launch(void* const* d_in, const int* in_sizes, int n_in,
                              void* d_out, int out_size) {
    const int*   text = (const int*)d_in[0];
    const int*   durs = (const int*)d_in[1];
    const float* emb  = (const float*)d_in[2];
    float* out = (float*)d_out;

    prep_kernel<<<BATCH, 544>>>(text, durs);
    dim3 grid(NTILES, BATCH);
    gauss_kernel<<<grid, NTH>>>(emb, out);
}